// round 1
// baseline (speedup 1.0000x reference)
#include <cuda_runtime.h>

// Problem constants
#define PB 16
#define PD 256
#define PT 4096
#define PK 2048
#define PBT (PB * PT)          // 65536
#define NDEC (PB * PD * PT)    // 16777216
#define EPSV 1e-5f

// Scratch (allocation-free rule: __device__ globals)
__device__ float g_emb[PK * PD];   // 2 MB, L2-resident
__device__ float g_e2[PK];
__device__ int   g_codes[PBT];

// ---------------------------------------------------------------------------
// Kernel 1: emb[k,d] = embedding_sum[k,d] / max(usage[k], eps);  e2[k] = |emb_k|^2
// ---------------------------------------------------------------------------
__global__ void prep_kernel(const float* __restrict__ esum,
                            const float* __restrict__ cu) {
    int k = blockIdx.x;
    int d = threadIdx.x;                    // 256 threads = one d each
    float u = fmaxf(cu[k], EPSV);
    float v = __fdiv_rn(esum[k * PD + d], u);   // IEEE division (match jax)
    g_emb[k * PD + d] = v;

    __shared__ float red[256];
    red[d] = v * v;
    __syncthreads();
    #pragma unroll
    for (int s = 128; s > 0; s >>= 1) {
        if (d < s) red[d] += red[d + s];
        __syncthreads();
    }
    if (d == 0) g_e2[k] = red[0];
}

// ---------------------------------------------------------------------------
// Kernel 2: fused GEMM + argmin.
// Block = 64 t-rows x all 2048 k, looped in k-tiles of 128, d-chunks of 32.
// Thread (tx,ty) in 16x16 owns a 4t x 8k micro-tile of accumulators.
// score(t,k) = e2[k] - 2 * dot(x_t, emb_k)   (x2 and sqrt dropped: monotonic)
// ---------------------------------------------------------------------------
__global__ __launch_bounds__(256, 2)
void argmin_kernel(const float* __restrict__ x, float* __restrict__ codes_out) {
    __shared__ float xs[32][64];        // 8 KB   [d][t]
    __shared__ float es[128][33];       // 16.9 KB [k][d] (+1 pad: no bank conflicts)
    __shared__ float e2s[128];
    __shared__ float rmin[16][64];
    __shared__ int   ridx[16][64];

    const int tid = threadIdx.x;
    const int tx = tid & 15;
    const int ty = tid >> 4;
    const long t0 = (long)blockIdx.x * 64;      // global row in [0, BT)
    const int  b  = (int)(t0 >> 12);            // / 4096 (tile never crosses b)
    const int  tl = (int)(t0 & 4095);
    const float* xb = x + ((long)b * PD * PT + tl);

    float best[4];
    int   bidx[4];
    #pragma unroll
    for (int i = 0; i < 4; i++) { best[i] = 3.4e38f; bidx[i] = 0; }

    for (int k0 = 0; k0 < PK; k0 += 128) {
        float acc[4][8];
        #pragma unroll
        for (int i = 0; i < 4; i++)
            #pragma unroll
            for (int j = 0; j < 8; j++) acc[i][j] = 0.0f;

        for (int dc = 0; dc < PD; dc += 32) {
            __syncthreads();
            // load x tile: 32 d x 64 t (coalesced over t)
            #pragma unroll
            for (int r = 0; r < 8; r++) {
                int i = tid + r * 256;
                int d = i >> 6, t = i & 63;
                xs[d][t] = xb[(long)(dc + d) * PT + t];
            }
            // load emb tile: 128 k x 32 d (coalesced over d)
            #pragma unroll
            for (int r = 0; r < 16; r++) {
                int i = tid + r * 256;
                int kk = i >> 5, d = i & 31;
                es[kk][d] = g_emb[(k0 + kk) * PD + dc + d];
            }
            if (dc == 0 && tid < 128) e2s[tid] = g_e2[k0 + tid];
            __syncthreads();

            #pragma unroll
            for (int d = 0; d < 32; d++) {
                float4 xv = *(const float4*)&xs[d][tx * 4];
                float xr[4] = {xv.x, xv.y, xv.z, xv.w};
                #pragma unroll
                for (int j = 0; j < 8; j++) {
                    float e = es[ty * 8 + j][d];   // broadcast across tx
                    #pragma unroll
                    for (int i = 0; i < 4; i++)
                        acc[i][j] = fmaf(xr[i], e, acc[i][j]);
                }
            }
        }
        // epilogue: running argmin (k ascending within thread -> '<' keeps first)
        #pragma unroll
        for (int j = 0; j < 8; j++) {
            int   k  = k0 + ty * 8 + j;
            float e2 = e2s[ty * 8 + j];
            #pragma unroll
            for (int i = 0; i < 4; i++) {
                float s = fmaf(-2.0f, acc[i][j], e2);
                if (s < best[i]) { best[i] = s; bidx[i] = k; }
            }
        }
    }

    __syncthreads();
    #pragma unroll
    for (int i = 0; i < 4; i++) {
        rmin[ty][tx * 4 + i] = best[i];
        ridx[ty][tx * 4 + i] = bidx[i];
    }
    __syncthreads();
    if (tid < 64) {
        float bv = rmin[0][tid];
        int   bk = ridx[0][tid];
        #pragma unroll
        for (int y = 1; y < 16; y++) {
            float v = rmin[y][tid];
            int   kk = ridx[y][tid];
            if (v < bv || (v == bv && kk < bk)) { bv = v; bk = kk; }
        }
        g_codes[t0 + tid] = bk;
        if (codes_out) codes_out[t0 + tid] = (float)bk;
    }
}

// ---------------------------------------------------------------------------
// Kernel 3: decoded[b,d,t] = emb[code[b,t], d]   (coalesced writes, L2 gathers)
// ---------------------------------------------------------------------------
__global__ void decode_kernel(float* __restrict__ dec) {
    long idx = (long)blockIdx.x * 256 + threadIdx.x;   // < NDEC
    int t = (int)(idx & 4095);
    int d = (int)((idx >> 12) & 255);
    int b = (int)(idx >> 20);
    int code = g_codes[b * PT + t];
    dec[idx] = g_emb[code * PD + d];
}

__global__ void codes_int_kernel(int* __restrict__ out) {
    int i = blockIdx.x * 256 + threadIdx.x;
    if (i < PBT) out[i] = g_codes[i];
}

// ---------------------------------------------------------------------------
extern "C" void kernel_launch(void* const* d_in, const int* in_sizes, int n_in,
                              void* d_out, int out_size) {
    const float* x    = (const float*)d_in[0];
    const float* esum = (const float*)d_in[1];
    const float* cu   = (const float*)d_in[2];

    prep_kernel<<<PK, 256>>>(esum, cu);

    float* codes_out = nullptr;
    float* dec_out   = nullptr;
    bool   codes_as_int = false;

    if (out_size == PBT + NDEC) {            // [codes | decoded] as f32
        codes_out = (float*)d_out;
        dec_out   = (float*)d_out + PBT;
    } else if (out_size == NDEC) {           // decoded only
        dec_out = (float*)d_out;
    } else if (out_size == PBT) {            // codes only (likely int32)
        codes_as_int = true;
    } else {                                 // fallback: fill what fits
        codes_out = (float*)d_out;
        if (out_size >= PBT + NDEC) dec_out = (float*)d_out + PBT;
    }

    argmin_kernel<<<PBT / 64, 256>>>(x, codes_out);

    if (codes_as_int)
        codes_int_kernel<<<(PBT + 255) / 256, 256>>>((int*)d_out);
    if (dec_out)
        decode_kernel<<<NDEC / 256, 256>>>(dec_out);
}